// round 7
// baseline (speedup 1.0000x reference)
#include <cuda_runtime.h>
#include <stdint.h>
#include <math.h>

#define B_   2
#define S_   1024
#define D_   1024
#define H_   16
#define DK_  64
#define DFF_ 2048
#define L_   4
#define BS_  (B_*S_)

extern __shared__ char dsmem[];

// ---------------- scratch ----------------------------------------------------
__device__ float    g_x[BS_*D_];          // residual stream (f32)
__device__ uint32_t g_x32[BS_*D_];        // tf32 bits of x
__device__ uint32_t g_q32[BS_*D_];
__device__ uint32_t g_k32[BS_*D_];
__device__ uint32_t g_v32[BS_*D_];
__device__ float    g_o[BS_*D_];
__device__ uint32_t g_h32[BS_*DFF_];
__device__ float    g_f[BS_*D_];
// tf32 weights (same [K][N] layout as inputs)
__device__ uint32_t g_wq32[L_*D_*D_];
__device__ uint32_t g_wk32[L_*D_*D_];
__device__ uint32_t g_wv32[L_*D_*D_];
__device__ uint32_t g_w132[L_*D_*DFF_];
__device__ uint32_t g_w232[L_*DFF_*D_];

__device__ __forceinline__ float gelu_tanh_f(float x) {
    float x3 = x * x * x;
    return 0.5f * x * (1.0f + tanhf(0.7978845608028654f * (x + 0.044715f * x3)));
}

__device__ __forceinline__ uint32_t f2tf(float f) {
    uint32_t u;
    asm("cvt.rna.tf32.f32 %0, %1;" : "=r"(u) : "f"(f));
    return u;
}

__device__ __forceinline__ void mma_tf32(float* c, const uint32_t* a, const uint32_t* b) {
    asm volatile(
        "mma.sync.aligned.m16n8k8.row.col.f32.tf32.tf32.f32 "
        "{%0,%1,%2,%3}, {%4,%5,%6,%7}, {%8,%9}, {%0,%1,%2,%3};"
        : "+f"(c[0]), "+f"(c[1]), "+f"(c[2]), "+f"(c[3])
        : "r"(a[0]), "r"(a[1]), "r"(a[2]), "r"(a[3]), "r"(b[0]), "r"(b[1]));
}

__device__ __forceinline__ void cpa16(uint32_t saddr, const void* gptr) {
    asm volatile("cp.async.cg.shared.global [%0], [%1], 16;" :: "r"(saddr), "l"(gptr));
}
#define CP_COMMIT()  asm volatile("cp.async.commit_group;")
#define CP_WAIT(n)   asm volatile("cp.async.wait_group %0;" :: "n"(n))

// =============================================================================
// Pipelined tf32 GEMM: C[M,N] = A[M,K] @ W[K,N], operands PRE-CONVERTED tf32.
// 128x128 tile, BK=32, 3-stage cp.async, 8 warps (2Mx4N).
// EPI 0: C -> u32 tf32 out (q/k/v by z). EPI 1: C = acc + bias -> f32.
// EPI 2: C = tf32(gelu(acc + bias)) -> u32.
// =============================================================================
#define GA_STRIDE 36
#define GB_STRIDE 132
#define GA_ELEMS  (128*GA_STRIDE)
#define GB_ELEMS  (32*GB_STRIDE)
#define GEMM_SMEM ((3*GA_ELEMS + 3*GB_ELEMS)*4)

template<int EPI>
__global__ __launch_bounds__(256)
void gemm_pipe(const uint32_t* __restrict__ A,
               const uint32_t* __restrict__ W0, const uint32_t* __restrict__ W1,
               const uint32_t* __restrict__ W2, const float* __restrict__ bias,
               float* __restrict__ Cf,
               uint32_t* __restrict__ C0, uint32_t* __restrict__ C1,
               uint32_t* __restrict__ C2,
               int N, int K) {
    uint32_t* AsBase = (uint32_t*)dsmem;
    uint32_t* BsBase = (uint32_t*)dsmem + 3*GA_ELEMS;

    const uint32_t* W = (blockIdx.z == 0) ? W0 : (blockIdx.z == 1) ? W1 : W2;
    uint32_t* Cu = (blockIdx.z == 0) ? C0 : (blockIdx.z == 1) ? C1 : C2;

    const int tid = threadIdx.x;
    const int row0 = blockIdx.y * 128, col0 = blockIdx.x * 128;
    const int w = tid >> 5, lane = tid & 31;
    const int wm = w >> 2, wn = w & 3;
    const int grp = lane >> 2, qd = lane & 3;
    const int nIter = K >> 5;

    uint32_t sA0 = (uint32_t)__cvta_generic_to_shared(AsBase);
    uint32_t sB0 = (uint32_t)__cvta_generic_to_shared(BsBase);

    #define LOAD_TILE(it, st) {                                                     \
        uint32_t sa = sA0 + (st)*GA_ELEMS*4;                                        \
        uint32_t sb = sB0 + (st)*GB_ELEMS*4;                                        \
        int kt = (it) << 5;                                                         \
        _Pragma("unroll")                                                           \
        for (int i = 0; i < 4; i++) {                                               \
            int idx = tid + i * 256;                                                \
            int r = idx >> 3, c16 = idx & 7;                                        \
            cpa16(sa + (r*GA_STRIDE + c16*4)*4,                                     \
                  &A[(size_t)(row0 + r) * K + kt + c16*4]);                         \
        }                                                                           \
        _Pragma("unroll")                                                           \
        for (int i = 0; i < 4; i++) {                                               \
            int idx = tid + i * 256;                                                \
            int r = idx >> 5, c4 = (idx & 31) * 4;                                  \
            cpa16(sb + (r*GB_STRIDE + c4)*4,                                        \
                  &W[(size_t)(kt + r) * N + col0 + c4]);                            \
        }                                                                           \
    }

    float acc[4][4][4] = {};

    LOAD_TILE(0, 0); CP_COMMIT();
    LOAD_TILE(1, 1); CP_COMMIT();

    for (int it = 0; it < nIter; it++) {
        CP_WAIT(1);
        __syncthreads();
        if (it + 2 < nIter) { LOAD_TILE(it + 2, (it + 2) % 3); }
        CP_COMMIT();

        const uint32_t* As = AsBase + (it % 3) * GA_ELEMS;
        const uint32_t* Bs = BsBase + (it % 3) * GB_ELEMS;
        #pragma unroll
        for (int kk = 0; kk < 4; kk++) {
            int kb = kk * 8;
            uint32_t af[4][4], bf[4][2];
            #pragma unroll
            for (int mf = 0; mf < 4; mf++) {
                int r = wm * 64 + mf * 16 + grp;
                af[mf][0] = As[r * GA_STRIDE + kb + qd];
                af[mf][1] = As[(r + 8) * GA_STRIDE + kb + qd];
                af[mf][2] = As[r * GA_STRIDE + kb + qd + 4];
                af[mf][3] = As[(r + 8) * GA_STRIDE + kb + qd + 4];
            }
            #pragma unroll
            for (int nf = 0; nf < 4; nf++) {
                int c = wn * 32 + nf * 8 + grp;
                bf[nf][0] = Bs[(kb + qd) * GB_STRIDE + c];
                bf[nf][1] = Bs[(kb + qd + 4) * GB_STRIDE + c];
            }
            #pragma unroll
            for (int mf = 0; mf < 4; mf++)
                #pragma unroll
                for (int nf = 0; nf < 4; nf++)
                    mma_tf32(acc[mf][nf], af[mf], bf[nf]);
        }
        __syncthreads();
    }
    #undef LOAD_TILE

    #pragma unroll
    for (int mf = 0; mf < 4; mf++) {
        int r = row0 + wm * 64 + mf * 16 + grp;
        #pragma unroll
        for (int nf = 0; nf < 4; nf++) {
            int c = col0 + wn * 32 + nf * 8 + 2 * qd;
            float* a = acc[mf][nf];
            if (EPI == 0) {
                Cu[(size_t)r * N + c]       = f2tf(a[0]);
                Cu[(size_t)r * N + c + 1]   = f2tf(a[1]);
                Cu[(size_t)(r + 8) * N + c] = f2tf(a[2]);
                Cu[(size_t)(r + 8) * N + c + 1] = f2tf(a[3]);
            } else if (EPI == 1) {
                float b0 = bias[c], b1 = bias[c + 1];
                Cf[(size_t)r * N + c]       = a[0] + b0;
                Cf[(size_t)r * N + c + 1]   = a[1] + b1;
                Cf[(size_t)(r + 8) * N + c] = a[2] + b0;
                Cf[(size_t)(r + 8) * N + c + 1] = a[3] + b1;
            } else {
                float b0 = bias[c], b1 = bias[c + 1];
                Cu[(size_t)r * N + c]       = f2tf(gelu_tanh_f(a[0] + b0));
                Cu[(size_t)r * N + c + 1]   = f2tf(gelu_tanh_f(a[1] + b1));
                Cu[(size_t)(r + 8) * N + c] = f2tf(gelu_tanh_f(a[2] + b0));
                Cu[(size_t)(r + 8) * N + c + 1] = f2tf(gelu_tanh_f(a[3] + b1));
            }
        }
    }
}

// =============================================================================
// Fused attention: per CTA = 32 q-rows of one (b,h). Q/K/V already tf32 bits.
// =============================================================================
#define FA_SSTRIDE 1028
#define FA_SBUF    (32*FA_SSTRIDE)
#define FA_QOFF    FA_SBUF
#define FA_KVOFF   (FA_SBUF + 32*68)
#define FA_KVBUF   (128*68)
#define FA_SMEM    ((FA_KVOFF + 2*FA_KVBUF)*4)

__global__ __launch_bounds__(256)
void fused_attn(const float* __restrict__ attn_bias, const int* __restrict__ mask,
                float* __restrict__ out) {
    float*    sS  = (float*)dsmem;
    uint32_t* Qs  = (uint32_t*)dsmem + FA_QOFF;
    uint32_t* KVb = (uint32_t*)dsmem + FA_KVOFF;

    const int tid = threadIdx.x;
    const int w = tid >> 5, lane = tid & 31;
    const int wm = w >> 2, wn = w & 3;
    const int grp = lane >> 2, qd = lane & 3;
    const int row0 = blockIdx.x * 32;
    const int z = blockIdx.y, b = z >> 4, h = z & 15;

    const uint32_t* Qg = g_q32 + (size_t)b*S_*D_ + h*DK_;
    const uint32_t* Kg = g_k32 + (size_t)b*S_*D_ + h*DK_;
    const uint32_t* Vg = g_v32 + (size_t)b*S_*D_ + h*DK_;

    uint32_t sQ  = (uint32_t)__cvta_generic_to_shared(Qs);
    uint32_t sKV = (uint32_t)__cvta_generic_to_shared(KVb);

    #pragma unroll
    for (int i = 0; i < 2; i++) {
        int idx = tid + i*256;
        int r = idx >> 4, c = (idx & 15)*4;
        cpa16(sQ + (r*68 + c)*4, &Qg[(size_t)(row0+r)*D_ + c]);
    }
    #pragma unroll
    for (int i = 0; i < 8; i++) {
        int idx = tid + i*256;
        int r = idx >> 4, c = (idx & 15)*4;
        cpa16(sKV + (r*68 + c)*4, &Kg[(size_t)r*D_ + c]);
    }
    CP_COMMIT();

    // ---- phase 1: S = scale * Q K^T ----
    for (int t = 0; t < 8; t++) {
        __syncthreads();
        if (t + 1 < 8) {
            uint32_t dst = sKV + ((t+1)&1)*FA_KVBUF*4;
            int key0 = (t+1)*128;
            #pragma unroll
            for (int i = 0; i < 8; i++) {
                int idx = tid + i*256;
                int r = idx >> 4, c = (idx & 15)*4;
                cpa16(dst + (r*68 + c)*4, &Kg[(size_t)(key0+r)*D_ + c]);
            }
        }
        CP_COMMIT();
        CP_WAIT(1);
        __syncthreads();

        const uint32_t* Ks = KVb + (t&1)*FA_KVBUF;
        float acc[4][4] = {};
        #pragma unroll
        for (int kb8 = 0; kb8 < 8; kb8++) {
            int kb = kb8 * 8;
            uint32_t af[4], bf[4][2];
            int r = wm*16 + grp;
            af[0] = Qs[r*68 + kb + qd];
            af[1] = Qs[(r+8)*68 + kb + qd];
            af[2] = Qs[r*68 + kb + qd + 4];
            af[3] = Qs[(r+8)*68 + kb + qd + 4];
            #pragma unroll
            for (int nf = 0; nf < 4; nf++) {
                int c = wn*32 + nf*8 + grp;
                bf[nf][0] = Ks[c*68 + kb + qd];
                bf[nf][1] = Ks[c*68 + kb + qd + 4];
            }
            #pragma unroll
            for (int nf = 0; nf < 4; nf++)
                mma_tf32(acc[nf], af, bf[nf]);
        }
        {
            int r = wm*16 + grp;
            #pragma unroll
            for (int nf = 0; nf < 4; nf++) {
                int c = t*128 + wn*32 + nf*8 + 2*qd;
                sS[r*FA_SSTRIDE + c]       = acc[nf][0] * 0.125f;
                sS[r*FA_SSTRIDE + c + 1]   = acc[nf][1] * 0.125f;
                sS[(r+8)*FA_SSTRIDE + c]   = acc[nf][2] * 0.125f;
                sS[(r+8)*FA_SSTRIDE + c+1] = acc[nf][3] * 0.125f;
            }
        }
    }
    __syncthreads();

    // prefetch V tile 0 (overlaps softmax)
    #pragma unroll
    for (int i = 0; i < 8; i++) {
        int idx = tid + i*256;
        int r = idx >> 4, c = (idx & 15)*4;
        cpa16(sKV + (r*68 + c)*4, &Vg[(size_t)r*D_ + c]);
    }
    CP_COMMIT();

    // ---- phase 2: softmax, warp per row ----
    {
        const float* biasZ = attn_bias + (size_t)z*S_*S_;
        float* outZ = out + (size_t)z*S_*S_;
        const int* maskB = mask + b*S_;
        #pragma unroll
        for (int ri = 0; ri < 4; ri++) {
            int r = w*4 + ri;
            const float* bRow = biasZ + (size_t)(row0+r)*S_;
            float* oRow = outZ + (size_t)(row0+r)*S_;
            float* sRow = sS + r*FA_SSTRIDE;
            float4 vals[8];
            float m = -INFINITY;
            #pragma unroll
            for (int j = 0; j < 8; j++) {
                int c = lane*4 + j*128;
                float4 sv = *(float4*)&sRow[c];
                float4 bv = *(const float4*)&bRow[c];
                int4 mk = *(const int4*)&maskB[c];
                float4 v;
                v.x = mk.x ? sv.x + bv.x : -9e15f;
                v.y = mk.y ? sv.y + bv.y : -9e15f;
                v.z = mk.z ? sv.z + bv.z : -9e15f;
                v.w = mk.w ? sv.w + bv.w : -9e15f;
                vals[j] = v;
                m = fmaxf(m, fmaxf(fmaxf(v.x, v.y), fmaxf(v.z, v.w)));
            }
            #pragma unroll
            for (int o = 16; o > 0; o >>= 1) m = fmaxf(m, __shfl_xor_sync(~0u, m, o));
            float sum = 0.f;
            #pragma unroll
            for (int j = 0; j < 8; j++) {
                float4 v = vals[j];
                v.x = __expf(v.x - m); v.y = __expf(v.y - m);
                v.z = __expf(v.z - m); v.w = __expf(v.w - m);
                vals[j] = v;
                sum += v.x + v.y + v.z + v.w;
            }
            #pragma unroll
            for (int o = 16; o > 0; o >>= 1) sum += __shfl_xor_sync(~0u, sum, o);
            float inv = 1.0f / sum;
            #pragma unroll
            for (int j = 0; j < 8; j++) {
                int c = lane*4 + j*128;
                float4 v = vals[j];
                v.x *= inv; v.y *= inv; v.z *= inv; v.w *= inv;
                *(float4*)&sRow[c] = v;
                *(float4*)&oRow[c] = v;
            }
        }
    }

    // ---- phase 3: O = P @ V ----
    float accO[2][4] = {};
    for (int t = 0; t < 8; t++) {
        __syncthreads();
        if (t + 1 < 8) {
            uint32_t dst = sKV + ((t+1)&1)*FA_KVBUF*4;
            int key0 = (t+1)*128;
            #pragma unroll
            for (int i = 0; i < 8; i++) {
                int idx = tid + i*256;
                int r = idx >> 4, c = (idx & 15)*4;
                cpa16(dst + (r*68 + c)*4, &Vg[(size_t)(key0+r)*D_ + c]);
            }
        }
        CP_COMMIT();
        CP_WAIT(1);
        __syncthreads();

        const uint32_t* Vs = KVb + (t&1)*FA_KVBUF;
        #pragma unroll
        for (int kb8 = 0; kb8 < 16; kb8++) {
            int kcol = t*128 + kb8*8;
            uint32_t af[4];
            int r = wm*16 + grp;
            af[0] = f2tf(sS[r*FA_SSTRIDE + kcol + qd]);
            af[1] = f2tf(sS[(r+8)*FA_SSTRIDE + kcol + qd]);
            af[2] = f2tf(sS[r*FA_SSTRIDE + kcol + qd + 4]);
            af[3] = f2tf(sS[(r+8)*FA_SSTRIDE + kcol + qd + 4]);
            #pragma unroll
            for (int nf = 0; nf < 2; nf++) {
                int c = wn*16 + nf*8 + grp;
                uint32_t bf[2];
                bf[0] = Vs[(kb8*8 + qd)*68 + c];
                bf[1] = Vs[(kb8*8 + qd + 4)*68 + c];
                mma_tf32(accO[nf], af, bf);
            }
        }
    }
    {
        float* Og = g_o + (size_t)b*S_*D_ + h*DK_;
        int r = row0 + wm*16 + grp;
        #pragma unroll
        for (int nf = 0; nf < 2; nf++) {
            int c = wn*16 + nf*8 + 2*qd;
            Og[(size_t)r*D_ + c]       = accO[nf][0];
            Og[(size_t)r*D_ + c + 1]   = accO[nf][1];
            Og[(size_t)(r+8)*D_ + c]   = accO[nf][2];
            Og[(size_t)(r+8)*D_ + c+1] = accO[nf][3];
        }
    }
}

// ---------------- x = LayerNorm(x + r), plus tf32 copy ----------------------
__global__ void add_ln_split(float* __restrict__ x, const float* __restrict__ r,
                             const float* __restrict__ g, const float* __restrict__ bb,
                             uint32_t* __restrict__ x32) {
    float* row = x + (size_t)blockIdx.x * D_;
    const float* rr = r + (size_t)blockIdx.x * D_;
    uint32_t* trow = x32 + (size_t)blockIdx.x * D_;
    __shared__ float red[256];
    __shared__ float red2[256];
    int t = threadIdx.x;
    float v[4];
    float s = 0.f, s2 = 0.f;
    #pragma unroll
    for (int i = 0; i < 4; i++) {
        v[i] = row[t + i * 256] + rr[t + i * 256];
        s += v[i]; s2 += v[i] * v[i];
    }
    red[t] = s; red2[t] = s2; __syncthreads();
    for (int st = 128; st > 0; st >>= 1) {
        if (t < st) { red[t] += red[t + st]; red2[t] += red2[t + st]; }
        __syncthreads();
    }
    float mu = red[0] * (1.0f / D_);
    float var = red2[0] * (1.0f / D_) - mu * mu;
    float inv = rsqrtf(var + 1e-6f);
    #pragma unroll
    for (int i = 0; i < 4; i++) {
        int c = t + i * 256;
        float o = (v[i] - mu) * inv * g[c] + bb[c];
        row[c] = o;
        trow[c] = f2tf(o);
    }
}

// ---------------- helpers ----------------------------------------------------
__global__ void split_copy(float* __restrict__ dst, uint32_t* __restrict__ dst32,
                           const float* __restrict__ src) {
    int i = (blockIdx.x * 256 + threadIdx.x) * 4;
    float4 v = *(const float4*)&src[i];
    *(float4*)&dst[i] = v;
    uint4 u = make_uint4(f2tf(v.x), f2tf(v.y), f2tf(v.z), f2tf(v.w));
    *(uint4*)&dst32[i] = u;
}

__global__ void cvt_w(uint32_t* __restrict__ dst, const float* __restrict__ src) {
    int i = (blockIdx.x * 256 + threadIdx.x) * 4;
    float4 v = *(const float4*)&src[i];
    uint4 u = make_uint4(f2tf(v.x), f2tf(v.y), f2tf(v.z), f2tf(v.w));
    *(uint4*)&dst[i] = u;
}

__global__ void copyk(float* __restrict__ dst, const float* __restrict__ src, int n) {
    int i = blockIdx.x * 256 + threadIdx.x;
    if (i < n) dst[i] = src[i];
}

// ---------------------------------------------------------------------------
extern "C" void kernel_launch(void* const* d_in, const int* in_sizes, int n_in,
                              void* d_out, int out_size) {
    const float* x_in      = (const float*)d_in[0];
    const int*   mask      = (const int*)d_in[1];
    const float* attn_bias = (const float*)d_in[2];
    const float* Wq        = (const float*)d_in[3];
    const float* Wk        = (const float*)d_in[4];
    const float* Wv        = (const float*)d_in[5];
    const float* ln1_g     = (const float*)d_in[6];
    const float* ln1_b     = (const float*)d_in[7];
    const float* W1        = (const float*)d_in[8];
    const float* b1        = (const float*)d_in[9];
    const float* W2        = (const float*)d_in[10];
    const float* b2        = (const float*)d_in[11];
    const float* ln2_g     = (const float*)d_in[12];
    const float* ln2_b     = (const float*)d_in[13];
    float* out = (float*)d_out;

    cudaFuncSetAttribute(gemm_pipe<0>, cudaFuncAttributeMaxDynamicSharedMemorySize, GEMM_SMEM);
    cudaFuncSetAttribute(gemm_pipe<1>, cudaFuncAttributeMaxDynamicSharedMemorySize, GEMM_SMEM);
    cudaFuncSetAttribute(gemm_pipe<2>, cudaFuncAttributeMaxDynamicSharedMemorySize, GEMM_SMEM);
    cudaFuncSetAttribute(fused_attn,   cudaFuncAttributeMaxDynamicSharedMemorySize, FA_SMEM);

    float *px, *po, *pf;
    uint32_t *px32, *pq32, *pk32, *pv32, *ph32;
    uint32_t *pwq32, *pwk32, *pwv32, *pw132, *pw232;
    cudaGetSymbolAddress((void**)&px,  g_x);
    cudaGetSymbolAddress((void**)&po,  g_o);
    cudaGetSymbolAddress((void**)&pf,  g_f);
    cudaGetSymbolAddress((void**)&px32, g_x32);
    cudaGetSymbolAddress((void**)&pq32, g_q32);
    cudaGetSymbolAddress((void**)&pk32, g_k32);
    cudaGetSymbolAddress((void**)&pv32, g_v32);
    cudaGetSymbolAddress((void**)&ph32, g_h32);
    cudaGetSymbolAddress((void**)&pwq32, g_wq32);
    cudaGetSymbolAddress((void**)&pwk32, g_wk32);
    cudaGetSymbolAddress((void**)&pwv32, g_wv32);
    cudaGetSymbolAddress((void**)&pw132, g_w132);
    cudaGetSymbolAddress((void**)&pw232, g_w232);

    const int nX = BS_ * D_;

    // one-time weight conversion to tf32
    cvt_w<<<(L_*D_*D_)   / 1024, 256>>>(pwq32, Wq);
    cvt_w<<<(L_*D_*D_)   / 1024, 256>>>(pwk32, Wk);
    cvt_w<<<(L_*D_*D_)   / 1024, 256>>>(pwv32, Wv);
    cvt_w<<<(L_*D_*DFF_) / 1024, 256>>>(pw132, W1);
    cvt_w<<<(L_*DFF_*D_) / 1024, 256>>>(pw232, W2);

    split_copy<<<nX / 1024, 256>>>(px, px32, x_in);

    dim3 gQKV(D_ / 128, BS_ / 128, 3);
    dim3 gFF1(DFF_ / 128, BS_ / 128, 1);
    dim3 gFF2(D_ / 128, BS_ / 128, 1);
    dim3 gFA(S_ / 32, B_ * H_);

    for (int n = 0; n < L_; n++) {
        float* scores = out + (size_t)n * B_ * H_ * S_ * S_;

        gemm_pipe<0><<<gQKV, 256, GEMM_SMEM>>>(
            px32,
            pwq32 + (size_t)n * D_ * D_, pwk32 + (size_t)n * D_ * D_,
            pwv32 + (size_t)n * D_ * D_, nullptr,
            nullptr, pq32, pk32, pv32, D_, D_);

        fused_attn<<<gFA, 256, FA_SMEM>>>(attn_bias, mask, scores);

        add_ln_split<<<BS_, 256>>>(px, po, ln1_g + n * D_, ln1_b + n * D_, px32);

        gemm_pipe<2><<<gFF1, 256, GEMM_SMEM>>>(
            px32,
            pw132 + (size_t)n * D_ * DFF_, pw132 + (size_t)n * D_ * DFF_,
            pw132 + (size_t)n * D_ * DFF_, b1 + n * DFF_,
            nullptr, ph32, ph32, ph32, DFF_, D_);

        gemm_pipe<1><<<gFF2, 256, GEMM_SMEM>>>(
            ph32,
            pw232 + (size_t)n * DFF_ * D_, pw232 + (size_t)n * DFF_ * D_,
            pw232 + (size_t)n * DFF_ * D_, b2 + n * D_,
            pf, nullptr, nullptr, nullptr, D_, DFF_);

        add_ln_split<<<BS_, 256>>>(px, pf, ln2_g + n * D_, ln2_b + n * D_, px32);
    }

    copyk<<<(nX + 255) / 256, 256>>>(out + (size_t)L_ * B_ * H_ * S_ * S_, px, nX);
}

// round 8
// speedup vs baseline: 1.4831x; 1.4831x over previous
#include <cuda_runtime.h>
#include <stdint.h>
#include <math.h>

#define B_   2
#define S_   1024
#define D_   1024
#define H_   16
#define DK_  64
#define DFF_ 2048
#define L_   4
#define BS_  (B_*S_)

// ---------------- scratch ----------------------------------------------------
__device__ float g_x[BS_*D_];
__device__ float g_q[BS_*D_];
__device__ float g_k[BS_*D_];
__device__ float g_v[BS_*D_];
__device__ float g_o[BS_*D_];
__device__ float g_h[BS_*DFF_];
__device__ float g_f[BS_*D_];

__device__ __forceinline__ float gelu_tanh_f(float x) {
    float x3 = x * x * x;
    return 0.5f * x * (1.0f + tanhf(0.7978845608028654f * (x + 0.044715f * x3)));
}

__device__ __forceinline__ uint32_t f2tf(float f) {
    uint32_t u;
    asm("cvt.rna.tf32.f32 %0, %1;" : "=r"(u) : "f"(f));
    return u;
}

__device__ __forceinline__ void mma_tf32(float* c, const uint32_t* a, const uint32_t* b) {
    asm volatile(
        "mma.sync.aligned.m16n8k8.row.col.f32.tf32.tf32.f32 "
        "{%0,%1,%2,%3}, {%4,%5,%6,%7}, {%8,%9}, {%0,%1,%2,%3};"
        : "+f"(c[0]), "+f"(c[1]), "+f"(c[2]), "+f"(c[3])
        : "r"(a[0]), "r"(a[1]), "r"(a[2]), "r"(a[3]), "r"(b[0]), "r"(b[1]));
}

__device__ __forceinline__ void cpa16(uint32_t saddr, const void* gptr) {
    asm volatile("cp.async.cg.shared.global [%0], [%1], 16;" :: "r"(saddr), "l"(gptr));
}
#define CP_COMMIT()  asm volatile("cp.async.commit_group;")
#define CP_WAIT(n)   asm volatile("cp.async.wait_group %0;" :: "n"(n))

// =============================================================================
// Pipelined GEMM: C[M,N] = A[M,K] @ W[K,N]. 128x128 tile, BK=32, 2-stage
// cp.async, 2 CTAs/SM. 8 warps (2Mx4N). EPI: 0 none, 1 +bias, 2 gelu(+bias).
// z selects fused QKV.
// =============================================================================
#define GA_STRIDE 36
#define GB_STRIDE 132
#define GA_ELEMS  (128*GA_STRIDE)
#define GB_ELEMS  (32*GB_STRIDE)
#define GEMM_SMEM ((2*GA_ELEMS + 2*GB_ELEMS)*4)

template<int EPI>
__global__ __launch_bounds__(256, 2)
void gemm_pipe(const float* __restrict__ A,
               const float* __restrict__ W0, const float* __restrict__ W1,
               const float* __restrict__ W2, const float* __restrict__ bias,
               float* __restrict__ C0, float* __restrict__ C1, float* __restrict__ C2,
               int N, int K) {
    extern __shared__ float smem[];
    float* AsBase = smem;
    float* BsBase = smem + 2*GA_ELEMS;

    const float* W = (blockIdx.z == 0) ? W0 : (blockIdx.z == 1) ? W1 : W2;
    float*       C = (blockIdx.z == 0) ? C0 : (blockIdx.z == 1) ? C1 : C2;

    const int tid = threadIdx.x;
    const int row0 = blockIdx.y * 128, col0 = blockIdx.x * 128;
    const int w = tid >> 5, lane = tid & 31;
    const int wm = w >> 2, wn = w & 3;
    const int grp = lane >> 2, qd = lane & 3;
    const int nIter = K >> 5;

    uint32_t sA0 = (uint32_t)__cvta_generic_to_shared(AsBase);
    uint32_t sB0 = (uint32_t)__cvta_generic_to_shared(BsBase);

    #define LOAD_TILE(it, st) {                                                     \
        uint32_t sa = sA0 + (st)*GA_ELEMS*4;                                        \
        uint32_t sb = sB0 + (st)*GB_ELEMS*4;                                        \
        int kt = (it) << 5;                                                         \
        _Pragma("unroll")                                                           \
        for (int i = 0; i < 4; i++) {                                               \
            int idx = tid + i * 256;                                                \
            int r = idx >> 3, c16 = idx & 7;                                        \
            cpa16(sa + (r*GA_STRIDE + c16*4)*4,                                     \
                  &A[(size_t)(row0 + r) * K + kt + c16*4]);                         \
        }                                                                           \
        _Pragma("unroll")                                                           \
        for (int i = 0; i < 4; i++) {                                               \
            int idx = tid + i * 256;                                                \
            int r = idx >> 5, c4 = (idx & 31) * 4;                                  \
            cpa16(sb + (r*GB_STRIDE + c4)*4,                                        \
                  &W[(size_t)(kt + r) * N + col0 + c4]);                            \
        }                                                                           \
    }

    float acc[4][4][4] = {};

    LOAD_TILE(0, 0); CP_COMMIT();

    for (int it = 0; it < nIter; it++) {
        CP_WAIT(0);
        __syncthreads();
        if (it + 1 < nIter) { LOAD_TILE(it + 1, (it + 1) & 1); CP_COMMIT(); }

        const float* As = AsBase + (it & 1) * GA_ELEMS;
        const float* Bs = BsBase + (it & 1) * GB_ELEMS;
        #pragma unroll
        for (int kk = 0; kk < 4; kk++) {
            int kb = kk * 8;
            uint32_t af[4][4], bf[4][2];
            #pragma unroll
            for (int mf = 0; mf < 4; mf++) {
                int r = wm * 64 + mf * 16 + grp;
                af[mf][0] = f2tf(As[r * GA_STRIDE + kb + qd]);
                af[mf][1] = f2tf(As[(r + 8) * GA_STRIDE + kb + qd]);
                af[mf][2] = f2tf(As[r * GA_STRIDE + kb + qd + 4]);
                af[mf][3] = f2tf(As[(r + 8) * GA_STRIDE + kb + qd + 4]);
            }
            #pragma unroll
            for (int nf = 0; nf < 4; nf++) {
                int c = wn * 32 + nf * 8 + grp;
                bf[nf][0] = f2tf(Bs[(kb + qd) * GB_STRIDE + c]);
                bf[nf][1] = f2tf(Bs[(kb + qd + 4) * GB_STRIDE + c]);
            }
            #pragma unroll
            for (int mf = 0; mf < 4; mf++)
                #pragma unroll
                for (int nf = 0; nf < 4; nf++)
                    mma_tf32(acc[mf][nf], af[mf], bf[nf]);
        }
        __syncthreads();
    }
    #undef LOAD_TILE

    #pragma unroll
    for (int mf = 0; mf < 4; mf++) {
        int r = row0 + wm * 64 + mf * 16 + grp;
        #pragma unroll
        for (int nf = 0; nf < 4; nf++) {
            int c = col0 + wn * 32 + nf * 8 + 2 * qd;
            float* a = acc[mf][nf];
            float v0 = a[0], v1 = a[1], v2 = a[2], v3 = a[3];
            if (EPI >= 1) {
                float b0 = bias[c], b1 = bias[c + 1];
                v0 += b0; v1 += b1; v2 += b0; v3 += b1;
            }
            if (EPI == 2) {
                v0 = gelu_tanh_f(v0); v1 = gelu_tanh_f(v1);
                v2 = gelu_tanh_f(v2); v3 = gelu_tanh_f(v3);
            }
            C[(size_t)r * N + c] = v0;       C[(size_t)r * N + c + 1] = v1;
            C[(size_t)(r + 8) * N + c] = v2; C[(size_t)(r + 8) * N + c + 1] = v3;
        }
    }
}

// =============================================================================
// Fused attention: per CTA = 32 query rows of one (b,h).  (identical to R4)
// =============================================================================
#define FA_SSTRIDE 1028
#define FA_SBUF    (32*FA_SSTRIDE)
#define FA_QOFF    FA_SBUF
#define FA_KVOFF   (FA_SBUF + 32*68)
#define FA_KVBUF   (128*68)
#define FA_SMEM    ((FA_KVOFF + 2*FA_KVBUF)*4)

__global__ __launch_bounds__(256)
void fused_attn(const float* __restrict__ attn_bias, const int* __restrict__ mask,
                float* __restrict__ out) {
    extern __shared__ float smem[];
    float* sS  = smem;
    float* Qs  = smem + FA_QOFF;
    float* KVb = smem + FA_KVOFF;

    const int tid = threadIdx.x;
    const int w = tid >> 5, lane = tid & 31;
    const int wm = w >> 2, wn = w & 3;
    const int grp = lane >> 2, qd = lane & 3;
    const int row0 = blockIdx.x * 32;
    const int z = blockIdx.y, b = z >> 4, h = z & 15;

    const float* Qg = g_q + (size_t)b*S_*D_ + h*DK_;
    const float* Kg = g_k + (size_t)b*S_*D_ + h*DK_;
    const float* Vg = g_v + (size_t)b*S_*D_ + h*DK_;

    uint32_t sQ  = (uint32_t)__cvta_generic_to_shared(Qs);
    uint32_t sKV = (uint32_t)__cvta_generic_to_shared(KVb);

    #pragma unroll
    for (int i = 0; i < 2; i++) {
        int idx = tid + i*256;
        int r = idx >> 4, c = (idx & 15)*4;
        cpa16(sQ + (r*68 + c)*4, &Qg[(size_t)(row0+r)*D_ + c]);
    }
    #pragma unroll
    for (int i = 0; i < 8; i++) {
        int idx = tid + i*256;
        int r = idx >> 4, c = (idx & 15)*4;
        cpa16(sKV + (r*68 + c)*4, &Kg[(size_t)r*D_ + c]);
    }
    CP_COMMIT();

    // ---- phase 1: S = scale * Q K^T ----
    for (int t = 0; t < 8; t++) {
        __syncthreads();
        if (t + 1 < 8) {
            uint32_t dst = sKV + ((t+1)&1)*FA_KVBUF*4;
            int key0 = (t+1)*128;
            #pragma unroll
            for (int i = 0; i < 8; i++) {
                int idx = tid + i*256;
                int r = idx >> 4, c = (idx & 15)*4;
                cpa16(dst + (r*68 + c)*4, &Kg[(size_t)(key0+r)*D_ + c]);
            }
        }
        CP_COMMIT();
        CP_WAIT(1);
        __syncthreads();

        const float* Ks = KVb + (t&1)*FA_KVBUF;
        float acc[4][4] = {};
        #pragma unroll
        for (int kb8 = 0; kb8 < 8; kb8++) {
            int kb = kb8 * 8;
            uint32_t af[4], bf[4][2];
            int r = wm*16 + grp;
            af[0] = f2tf(Qs[r*68 + kb + qd]);
            af[1] = f2tf(Qs[(r+8)*68 + kb + qd]);
            af[2] = f2tf(Qs[r*68 + kb + qd + 4]);
            af[3] = f2tf(Qs[(r+8)*68 + kb + qd + 4]);
            #pragma unroll
            for (int nf = 0; nf < 4; nf++) {
                int c = wn*32 + nf*8 + grp;
                bf[nf][0] = f2tf(Ks[c*68 + kb + qd]);
                bf[nf][1] = f2tf(Ks[c*68 + kb + qd + 4]);
            }
            #pragma unroll
            for (int nf = 0; nf < 4; nf++)
                mma_tf32(acc[nf], af, bf[nf]);
        }
        {
            int r = wm*16 + grp;
            #pragma unroll
            for (int nf = 0; nf < 4; nf++) {
                int c = t*128 + wn*32 + nf*8 + 2*qd;
                sS[r*FA_SSTRIDE + c]       = acc[nf][0] * 0.125f;
                sS[r*FA_SSTRIDE + c + 1]   = acc[nf][1] * 0.125f;
                sS[(r+8)*FA_SSTRIDE + c]   = acc[nf][2] * 0.125f;
                sS[(r+8)*FA_SSTRIDE + c+1] = acc[nf][3] * 0.125f;
            }
        }
    }
    __syncthreads();

    // prefetch V tile 0 (overlaps softmax)
    #pragma unroll
    for (int i = 0; i < 8; i++) {
        int idx = tid + i*256;
        int r = idx >> 4, c = (idx & 15)*4;
        cpa16(sKV + (r*68 + c)*4, &Vg[(size_t)r*D_ + c]);
    }
    CP_COMMIT();

    // ---- phase 2: softmax, warp per row ----
    {
        const float* biasZ = attn_bias + (size_t)z*S_*S_;
        float* outZ = out + (size_t)z*S_*S_;
        const int* maskB = mask + b*S_;
        #pragma unroll
        for (int ri = 0; ri < 4; ri++) {
            int r = w*4 + ri;
            const float* bRow = biasZ + (size_t)(row0+r)*S_;
            float* oRow = outZ + (size_t)(row0+r)*S_;
            float* sRow = sS + r*FA_SSTRIDE;
            float4 vals[8];
            float m = -INFINITY;
            #pragma unroll
            for (int j = 0; j < 8; j++) {
                int c = lane*4 + j*128;
                float4 sv = *(float4*)&sRow[c];
                float4 bv = *(const float4*)&bRow[c];
                int4 mk = *(const int4*)&maskB[c];
                float4 v;
                v.x = mk.x ? sv.x + bv.x : -9e15f;
                v.y = mk.y ? sv.y + bv.y : -9e15f;
                v.z = mk.z ? sv.z + bv.z : -9e15f;
                v.w = mk.w ? sv.w + bv.w : -9e15f;
                vals[j] = v;
                m = fmaxf(m, fmaxf(fmaxf(v.x, v.y), fmaxf(v.z, v.w)));
            }
            #pragma unroll
            for (int o = 16; o > 0; o >>= 1) m = fmaxf(m, __shfl_xor_sync(~0u, m, o));
            float sum = 0.f;
            #pragma unroll
            for (int j = 0; j < 8; j++) {
                float4 v = vals[j];
                v.x = __expf(v.x - m); v.y = __expf(v.y - m);
                v.z = __expf(v.z - m); v.w = __expf(v.w - m);
                vals[j] = v;
                sum += v.x + v.y + v.z + v.w;
            }
            #pragma unroll
            for (int o = 16; o > 0; o >>= 1) sum += __shfl_xor_sync(~0u, sum, o);
            float inv = 1.0f / sum;
            #pragma unroll
            for (int j = 0; j < 8; j++) {
                int c = lane*4 + j*128;
                float4 v = vals[j];
                v.x *= inv; v.y *= inv; v.z *= inv; v.w *= inv;
                *(float4*)&sRow[c] = v;
                *(float4*)&oRow[c] = v;
            }
        }
    }

    // ---- phase 3: O = P @ V ----
    float accO[2][4] = {};
    for (int t = 0; t < 8; t++) {
        __syncthreads();
        if (t + 1 < 8) {
            uint32_t dst = sKV + ((t+1)&1)*FA_KVBUF*4;
            int key0 = (t+1)*128;
            #pragma unroll
            for (int i = 0; i < 8; i++) {
                int idx = tid + i*256;
                int r = idx >> 4, c = (idx & 15)*4;
                cpa16(dst + (r*68 + c)*4, &Vg[(size_t)(key0+r)*D_ + c]);
            }
        }
        CP_COMMIT();
        CP_WAIT(1);
        __syncthreads();

        const float* Vs = KVb + (t&1)*FA_KVBUF;
        #pragma unroll
        for (int kb8 = 0; kb8 < 16; kb8++) {
            int kcol = t*128 + kb8*8;
            uint32_t af[4];
            int r = wm*16 + grp;
            af[0] = f2tf(sS[r*FA_SSTRIDE + kcol + qd]);
            af[1] = f2tf(sS[(r+8)*FA_SSTRIDE + kcol + qd]);
            af[2] = f2tf(sS[r*FA_SSTRIDE + kcol + qd + 4]);
            af[3] = f2tf(sS[(r+8)*FA_SSTRIDE + kcol + qd + 4]);
            #pragma unroll
            for (int nf = 0; nf < 2; nf++) {
                int c = wn*16 + nf*8 + grp;
                uint32_t bf[2];
                bf[0] = f2tf(Vs[(kb8*8 + qd)*68 + c]);
                bf[1] = f2tf(Vs[(kb8*8 + qd + 4)*68 + c]);
                mma_tf32(accO[nf], af, bf);
            }
        }
    }
    {
        float* Og = g_o + (size_t)b*S_*D_ + h*DK_;
        int r = row0 + wm*16 + grp;
        #pragma unroll
        for (int nf = 0; nf < 2; nf++) {
            int c = wn*16 + nf*8 + 2*qd;
            Og[(size_t)r*D_ + c]       = accO[nf][0];
            Og[(size_t)r*D_ + c + 1]   = accO[nf][1];
            Og[(size_t)(r+8)*D_ + c]   = accO[nf][2];
            Og[(size_t)(r+8)*D_ + c+1] = accO[nf][3];
        }
    }
}

// ---------------- x = LayerNorm(x + r) * g + b ------------------------------
__global__ void add_ln(float* __restrict__ x, const float* __restrict__ r,
                       const float* __restrict__ g, const float* __restrict__ bb) {
    float* row = x + (size_t)blockIdx.x * D_;
    const float* rr = r + (size_t)blockIdx.x * D_;
    __shared__ float red[256];
    __shared__ float red2[256];
    int t = threadIdx.x;
    float v[4];
    float s = 0.f, s2 = 0.f;
    #pragma unroll
    for (int i = 0; i < 4; i++) {
        v[i] = row[t + i * 256] + rr[t + i * 256];
        s += v[i]; s2 += v[i] * v[i];
    }
    red[t] = s; red2[t] = s2; __syncthreads();
    for (int st = 128; st > 0; st >>= 1) {
        if (t < st) { red[t] += red[t + st]; red2[t] += red2[t + st]; }
        __syncthreads();
    }
    float mu = red[0] * (1.0f / D_);
    float var = red2[0] * (1.0f / D_) - mu * mu;
    float inv = rsqrtf(var + 1e-6f);
    #pragma unroll
    for (int i = 0; i < 4; i++) {
        int c = t + i * 256;
        row[c] = (v[i] - mu) * inv * g[c] + bb[c];
    }
}

__global__ void copyk(float* __restrict__ dst, const float* __restrict__ src, int n) {
    int i = blockIdx.x * 256 + threadIdx.x;
    if (i < n) dst[i] = src[i];
}

// ---------------------------------------------------------------------------
extern "C" void kernel_launch(void* const* d_in, const int* in_sizes, int n_in,
                              void* d_out, int out_size) {
    const float* x_in      = (const float*)d_in[0];
    const int*   mask      = (const int*)d_in[1];
    const float* attn_bias = (const float*)d_in[2];
    const float* Wq        = (const float*)d_in[3];
    const float* Wk        = (const float*)d_in[4];
    const float* Wv        = (const float*)d_in[5];
    const float* ln1_g     = (const float*)d_in[6];
    const float* ln1_b     = (const float*)d_in[7];
    const float* W1        = (const float*)d_in[8];
    const float* b1        = (const float*)d_in[9];
    const float* W2        = (const float*)d_in[10];
    const float* b2        = (const float*)d_in[11];
    const float* ln2_g     = (const float*)d_in[12];
    const float* ln2_b     = (const float*)d_in[13];
    float* out = (float*)d_out;

    cudaFuncSetAttribute(gemm_pipe<0>, cudaFuncAttributeMaxDynamicSharedMemorySize, GEMM_SMEM);
    cudaFuncSetAttribute(gemm_pipe<1>, cudaFuncAttributeMaxDynamicSharedMemorySize, GEMM_SMEM);
    cudaFuncSetAttribute(gemm_pipe<2>, cudaFuncAttributeMaxDynamicSharedMemorySize, GEMM_SMEM);
    cudaFuncSetAttribute(fused_attn,   cudaFuncAttributeMaxDynamicSharedMemorySize, FA_SMEM);

    float *px, *pq, *pk, *pv, *po, *ph, *pf;
    cudaGetSymbolAddress((void**)&px, g_x);
    cudaGetSymbolAddress((void**)&pq, g_q);
    cudaGetSymbolAddress((void**)&pk, g_k);
    cudaGetSymbolAddress((void**)&pv, g_v);
    cudaGetSymbolAddress((void**)&po, g_o);
    cudaGetSymbolAddress((void**)&ph, g_h);
    cudaGetSymbolAddress((void**)&pf, g_f);

    const int nX = BS_ * D_;
    copyk<<<(nX + 255) / 256, 256>>>(px, x_in, nX);

    dim3 gQKV(D_ / 128, BS_ / 128, 3);
    dim3 gFF1(DFF_ / 128, BS_ / 128, 1);
    dim3 gFF2(D_ / 128, BS_ / 128, 1);
    dim3 gFA(S_ / 32, B_ * H_);

    for (int n = 0; n < L_; n++) {
        const float* wq = Wq + (size_t)n * D_ * D_;
        const float* wk = Wk + (size_t)n * D_ * D_;
        const float* wv = Wv + (size_t)n * D_ * D_;
        float* scores = out + (size_t)n * B_ * H_ * S_ * S_;

        gemm_pipe<0><<<gQKV, 256, GEMM_SMEM>>>(px, wq, wk, wv, nullptr,
                                               pq, pk, pv, D_, D_);

        fused_attn<<<gFA, 256, FA_SMEM>>>(attn_bias, mask, scores);

        add_ln<<<BS_, 256>>>(px, po, ln1_g + n * D_, ln1_b + n * D_);

        const float* w1 = W1 + (size_t)n * D_ * DFF_;
        const float* w2 = W2 + (size_t)n * DFF_ * D_;
        gemm_pipe<2><<<gFF1, 256, GEMM_SMEM>>>(px, w1, w1, w1, b1 + n * DFF_,
                                               ph, ph, ph, DFF_, D_);
        gemm_pipe<1><<<gFF2, 256, GEMM_SMEM>>>(ph, w2, w2, w2, b2 + n * D_,
                                               pf, pf, pf, D_, DFF_);

        add_ln<<<BS_, 256>>>(px, pf, ln2_g + n * D_, ln2_b + n * D_);
    }

    copyk<<<(nX + 255) / 256, 256>>>(out + (size_t)L_ * B_ * H_ * S_ * S_, px, nX);
}